// round 1
// baseline (speedup 1.0000x reference)
#include <cuda_runtime.h>
#include <math.h>

#define DM   1024
#define DF   4096
#define NT   4096    // B*L tokens
#define LSEQ 2048
#define NH   16
#define DH   64
#define EPSV 1e-6f

// ---------------- scratch (no allocation allowed) ----------------
__device__ float g_qkv [NT * 3 * DM];  // 50 MB
__device__ float g_attn[NT * DM];
__device__ float g_proj[NT * DM];
__device__ float g_x1  [NT * DM];
__device__ float g_h   [NT * DF];      // 67 MB
__device__ float g_mlp [NT * DM];

// ---------------- SGEMM: C[M,N] = A[M,K] @ B[K,N] + bias, optional relu ----------------
#define BM 128
#define BN 128
#define BK 8
#define TM 8
#define TN 8

__global__ __launch_bounds__(256) void sgemm_bias(
    const float* __restrict__ A, const float* __restrict__ B,
    const float* __restrict__ bias, float* __restrict__ C,
    int M, int N, int K, int do_relu)
{
    __shared__ float As[BK][BM];
    __shared__ float Bs[BK][BN];

    const int tid = threadIdx.x;
    const int bx = blockIdx.x, by = blockIdx.y;

    // A tile: 128 rows x 8 cols = 256 float4 (2 float4 per row)
    const int arow  = tid >> 1;          // 0..127
    const int acol4 = (tid & 1) * 4;     // 0 or 4
    // B tile: 8 rows x 128 cols = 256 float4
    const int brow  = tid >> 5;          // 0..7
    const int bcol4 = (tid & 31) * 4;    // 0..124

    const float* Ab = A + (size_t)(by * BM) * K;
    const float* Bb = B + bx * BN;

    const int ty = tid >> 4, tx = tid & 15;

    float acc[TM][TN];
    #pragma unroll
    for (int i = 0; i < TM; i++)
        #pragma unroll
        for (int j = 0; j < TN; j++) acc[i][j] = 0.f;

    for (int k0 = 0; k0 < K; k0 += BK) {
        float4 av = *(const float4*)(Ab + (size_t)arow * K + k0 + acol4);
        As[acol4 + 0][arow] = av.x;
        As[acol4 + 1][arow] = av.y;
        As[acol4 + 2][arow] = av.z;
        As[acol4 + 3][arow] = av.w;
        *(float4*)&Bs[brow][bcol4] = *(const float4*)(Bb + (size_t)(k0 + brow) * N + bcol4);
        __syncthreads();

        #pragma unroll
        for (int k = 0; k < BK; k++) {
            float ar[TM], br[TN];
            float4 a0 = *(float4*)&As[k][ty * TM];
            float4 a1 = *(float4*)&As[k][ty * TM + 4];
            ar[0]=a0.x; ar[1]=a0.y; ar[2]=a0.z; ar[3]=a0.w;
            ar[4]=a1.x; ar[5]=a1.y; ar[6]=a1.z; ar[7]=a1.w;
            float4 b0 = *(float4*)&Bs[k][tx * TN];
            float4 b1 = *(float4*)&Bs[k][tx * TN + 4];
            br[0]=b0.x; br[1]=b0.y; br[2]=b0.z; br[3]=b0.w;
            br[4]=b1.x; br[5]=b1.y; br[6]=b1.z; br[7]=b1.w;
            #pragma unroll
            for (int i = 0; i < TM; i++)
                #pragma unroll
                for (int j = 0; j < TN; j++)
                    acc[i][j] += ar[i] * br[j];
        }
        __syncthreads();
    }

    #pragma unroll
    for (int i = 0; i < TM; i++) {
        const size_t r = (size_t)(by * BM + ty * TM + i);
        #pragma unroll
        for (int j = 0; j < TN; j += 4) {
            const int c = bx * BN + tx * TN + j;
            float4 o;
            o.x = acc[i][j + 0] + bias[c + 0];
            o.y = acc[i][j + 1] + bias[c + 1];
            o.z = acc[i][j + 2] + bias[c + 2];
            o.w = acc[i][j + 3] + bias[c + 3];
            if (do_relu) {
                o.x = fmaxf(o.x, 0.f); o.y = fmaxf(o.y, 0.f);
                o.z = fmaxf(o.z, 0.f); o.w = fmaxf(o.w, 0.f);
            }
            *(float4*)(C + r * N + c) = o;
        }
    }
}

// ---------------- causal flash attention (fp32) ----------------
// qkv: [NT][3*DM] where per-token layout is [3][H][DH]
// attn out: [NT][DM] = [token][h*64+d]
#define AT_BM 128   // query rows per block (1 thread each)
#define AT_BN 64    // keys per SMEM tile

__global__ __launch_bounds__(128) void attention_kernel(
    const float* __restrict__ qkv, float* __restrict__ attn)
{
    __shared__ float Ks[AT_BN][DH];
    __shared__ float Vs[AT_BN][DH];

    const int bh = blockIdx.y;          // 0..31
    const int b  = bh >> 4;
    const int h  = bh & 15;
    const int q0 = blockIdx.x * AT_BM;  // query offset within L
    const int tid = threadIdx.x;
    const int row = q0 + tid;           // local l of this thread's query

    const float* base = qkv + (size_t)b * LSEQ * (3 * DM);

    // q in registers, scale 1/sqrt(64) folded in
    float q[DH];
    {
        const float* qp = base + (size_t)row * (3 * DM) + h * DH;
        #pragma unroll
        for (int d = 0; d < DH; d++) q[d] = qp[d] * 0.125f;
    }

    float o[DH];
    #pragma unroll
    for (int d = 0; d < DH; d++) o[d] = 0.f;
    float m = -INFINITY, lsum = 0.f;

    const int kmax = q0 + AT_BM;  // keys needed: up to q0+127
    for (int j0 = 0; j0 < kmax; j0 += AT_BN) {
        __syncthreads();
        // cooperative tile load: 64 rows * 16 float4 each for K and V
        for (int i = tid; i < AT_BN * (DH / 4); i += AT_BM) {
            const int r = i >> 4, c4 = (i & 15) * 4;
            const float* kp = base + (size_t)(j0 + r) * (3 * DM) + DM + h * DH + c4;
            *(float4*)&Ks[r][c4] = *(const float4*)kp;
            *(float4*)&Vs[r][c4] = *(const float4*)(kp + DM);
        }
        __syncthreads();

        // process 16-key chunks with online softmax
        for (int jc = 0; jc < AT_BN; jc += 16) {
            if (j0 + jc > row) break;   // fully masked from here on (per-thread)
            float s[16];
            #pragma unroll
            for (int jj = 0; jj < 16; jj++) {
                float a = 0.f;
                #pragma unroll
                for (int d4 = 0; d4 < DH / 4; d4++) {
                    float4 kv = *(float4*)&Ks[jc + jj][d4 * 4];
                    a += q[d4*4+0]*kv.x + q[d4*4+1]*kv.y + q[d4*4+2]*kv.z + q[d4*4+3]*kv.w;
                }
                s[jj] = (j0 + jc + jj <= row) ? a : -INFINITY;
            }
            float cmax = s[0];
            #pragma unroll
            for (int jj = 1; jj < 16; jj++) cmax = fmaxf(cmax, s[jj]);
            const float nm = fmaxf(m, cmax);
            const float scale = __expf(m - nm);   // m=-inf first time -> 0
            m = nm;
            lsum *= scale;
            #pragma unroll
            for (int d = 0; d < DH; d++) o[d] *= scale;
            #pragma unroll
            for (int jj = 0; jj < 16; jj++) {
                const float p = __expf(s[jj] - nm);  // -inf -> 0
                lsum += p;
                #pragma unroll
                for (int d4 = 0; d4 < DH / 4; d4++) {
                    float4 vv = *(float4*)&Vs[jc + jj][d4 * 4];
                    o[d4*4+0] += p * vv.x;
                    o[d4*4+1] += p * vv.y;
                    o[d4*4+2] += p * vv.z;
                    o[d4*4+3] += p * vv.w;
                }
            }
        }
    }

    const float inv = 1.f / lsum;
    float* op = attn + ((size_t)(b * LSEQ + row)) * DM + h * DH;
    #pragma unroll
    for (int d4 = 0; d4 < DH / 4; d4++) {
        float4 ov;
        ov.x = o[d4*4+0] * inv; ov.y = o[d4*4+1] * inv;
        ov.z = o[d4*4+2] * inv; ov.w = o[d4*4+3] * inv;
        *(float4*)(op + d4 * 4) = ov;
    }
}

// ---------------- fused residual + LayerNorm (matches ref: (n-1) var, std+eps) ----------------
__global__ __launch_bounds__(256) void ln_residual(
    const float* __restrict__ X, const float* __restrict__ Y,
    const float* __restrict__ gamma, const float* __restrict__ beta,
    float* __restrict__ out)
{
    __shared__ float sbuf[DM];
    __shared__ float red[8];

    const int row = blockIdx.x;
    const int tid = threadIdx.x;
    const int lane = tid & 31, warp = tid >> 5;
    const float* xr = X + (size_t)row * DM;
    const float* yr = Y + (size_t)row * DM;

    float lsum = 0.f;
    for (int i = tid; i < DM; i += 256) {
        const float v = xr[i] + yr[i];
        sbuf[i] = v;
        lsum += v;
    }
    #pragma unroll
    for (int off = 16; off > 0; off >>= 1) lsum += __shfl_down_sync(0xffffffffu, lsum, off);
    if (lane == 0) red[warp] = lsum;
    __syncthreads();
    float tot = 0.f;
    if (tid < 8) tot = red[tid];
    if (warp == 0) {
        #pragma unroll
        for (int off = 4; off > 0; off >>= 1) tot += __shfl_down_sync(0xffu, tot, off);
    }
    __shared__ float s_mean;
    if (tid == 0) s_mean = tot / (float)DM;
    __syncthreads();
    const float mean = s_mean;

    float lss = 0.f;
    for (int i = tid; i < DM; i += 256) {
        const float d = sbuf[i] - mean;
        lss += d * d;
    }
    #pragma unroll
    for (int off = 16; off > 0; off >>= 1) lss += __shfl_down_sync(0xffffffffu, lss, off);
    __syncthreads();
    if (lane == 0) red[warp] = lss;
    __syncthreads();
    float tot2 = 0.f;
    if (tid < 8) tot2 = red[tid];
    if (warp == 0) {
        #pragma unroll
        for (int off = 4; off > 0; off >>= 1) tot2 += __shfl_down_sync(0xffu, tot2, off);
    }
    __shared__ float s_inv;
    if (tid == 0) {
        const float var = tot2 / (float)(DM - 1);
        s_inv = 1.f / (sqrtf(var) + EPSV);
    }
    __syncthreads();
    const float inv = s_inv;

    float* orow = out + (size_t)row * DM;
    for (int i = tid; i < DM; i += 256)
        orow[i] = (sbuf[i] - mean) * inv * gamma[i] + beta[i];
}

// ---------------- launch ----------------
extern "C" void kernel_launch(void* const* d_in, const int* in_sizes, int n_in,
                              void* d_out, int out_size)
{
    const float* x    = (const float*)d_in[0];
    // d_in[1] = mask (unused; causality is implemented directly)
    const float* Wqkv = (const float*)d_in[2];
    const float* bqkv = (const float*)d_in[3];
    const float* Wo   = (const float*)d_in[4];
    const float* bo   = (const float*)d_in[5];
    const float* W1   = (const float*)d_in[6];
    const float* b1   = (const float*)d_in[7];
    const float* W2   = (const float*)d_in[8];
    const float* b2   = (const float*)d_in[9];
    const float* ln1a = (const float*)d_in[10];
    const float* ln1b = (const float*)d_in[11];
    const float* ln2a = (const float*)d_in[12];
    const float* ln2b = (const float*)d_in[13];
    float* out = (float*)d_out;

    float *qkv, *attn, *proj, *x1, *hbuf, *mlp;
    cudaGetSymbolAddress((void**)&qkv,  g_qkv);
    cudaGetSymbolAddress((void**)&attn, g_attn);
    cudaGetSymbolAddress((void**)&proj, g_proj);
    cudaGetSymbolAddress((void**)&x1,   g_x1);
    cudaGetSymbolAddress((void**)&hbuf, g_h);
    cudaGetSymbolAddress((void**)&mlp,  g_mlp);

    // 1) QKV projection: [4096,1024] @ [1024,3072]
    sgemm_bias<<<dim3(3 * DM / BN, NT / BM), 256>>>(x, Wqkv, bqkv, qkv, NT, 3 * DM, DM, 0);
    // 2) causal attention
    attention_kernel<<<dim3(LSEQ / AT_BM, 2 * NH), 128>>>(qkv, attn);
    // 3) output projection
    sgemm_bias<<<dim3(DM / BN, NT / BM), 256>>>(attn, Wo, bo, proj, NT, DM, DM, 0);
    // 4) LN1(x + attn_out)
    ln_residual<<<NT, 256>>>(x, proj, ln1a, ln1b, x1);
    // 5) FFN up + relu: [4096,1024] @ [1024,4096]
    sgemm_bias<<<dim3(DF / BN, NT / BM), 256>>>(x1, W1, b1, hbuf, NT, DF, DM, 1);
    // 6) FFN down: [4096,4096] @ [4096,1024]
    sgemm_bias<<<dim3(DM / BN, NT / BM), 256>>>(hbuf, W2, b2, mlp, NT, DM, DF, 0);
    // 7) LN2(x1 + mlp_out) -> final output
    ln_residual<<<NT, 256>>>(x1, mlp, ln2a, ln2b, out);
}

// round 2
// speedup vs baseline: 1.8172x; 1.8172x over previous
#include <cuda_runtime.h>
#include <math.h>

#define DM   1024
#define DF   4096
#define NT   4096    // B*L tokens
#define LSEQ 2048
#define NH   16
#define DH   64
#define EPSV 1e-6f

// ---------------- scratch (no allocation allowed) ----------------
__device__ float g_qkv [NT * 3 * DM];
__device__ float g_attn[NT * DM];
__device__ float g_proj[NT * DM];
__device__ float g_x1  [NT * DM];
__device__ float g_h   [NT * DF];
__device__ float g_mlp [NT * DM];

// ================= TF32 tensor-core GEMM =================
// C[M,N] = A[M,K] @ B[K,N] + bias, optional relu.
// BM=BN=128, BK=16. 256 threads = 8 warps (2x4), warp tile 64x32,
// mma.sync.m16n8k8.tf32 with fp32 accumulate.

#define GBM 128
#define GBN 128
#define GBK 16
#define AS_STR 20    // padded row stride for As[m][k]
#define BS_STR 136   // padded row stride for Bs[k][n]

__device__ __forceinline__ unsigned f2tf32(float f) {
    unsigned r;
    asm("cvt.rna.tf32.f32 %0, %1;" : "=r"(r) : "f"(f));
    return r;
}

__device__ __forceinline__ void mma_tf32(float c[4], const unsigned a[4], const unsigned b[2]) {
    asm volatile(
        "mma.sync.aligned.m16n8k8.row.col.f32.tf32.tf32.f32 "
        "{%0,%1,%2,%3}, {%4,%5,%6,%7}, {%8,%9}, {%0,%1,%2,%3};"
        : "+f"(c[0]), "+f"(c[1]), "+f"(c[2]), "+f"(c[3])
        : "r"(a[0]), "r"(a[1]), "r"(a[2]), "r"(a[3]), "r"(b[0]), "r"(b[1]));
}

__global__ __launch_bounds__(256) void tgemm_bias(
    const float* __restrict__ A, const float* __restrict__ B,
    const float* __restrict__ bias, float* __restrict__ C,
    int M, int N, int K, int do_relu)
{
    __shared__ unsigned As[2][GBM * AS_STR];
    __shared__ unsigned Bs[2][GBK * BS_STR];

    const int tid = threadIdx.x;
    const int bx = blockIdx.x, by = blockIdx.y;
    const int lane = tid & 31, warp = tid >> 5;
    const int wm = (warp >> 2) * 64;   // warp row offset in tile
    const int wn = (warp & 3) * 32;    // warp col offset in tile
    const int lr = lane >> 2, lc = lane & 3;

    // staging indices (2 float4 per thread for each of A,B)
    // A: idx -> row=idx>>2 (0..127), col=(idx&3)*4 of 16
    // B: idx -> row=idx>>5 (0..15),  col=(idx&31)*4 of 128
    const int a_row0 = tid >> 2,        a_col = (tid & 3) * 4;
    const int b_row0 = tid >> 5,        b_col = (tid & 31) * 4;

    const float* Ab = A + (size_t)(by * GBM) * K;
    const float* Bb = B + bx * GBN;

    float acc[4][4][4];
    #pragma unroll
    for (int i = 0; i < 4; i++)
        #pragma unroll
        for (int j = 0; j < 4; j++)
            #pragma unroll
            for (int r = 0; r < 4; r++) acc[i][j][r] = 0.f;

    const int ntiles = K / GBK;

    float4 pa0, pa1, pb0, pb1;

    // ---- load tile 0 ----
    pa0 = *(const float4*)(Ab + (size_t)a_row0        * K + a_col);
    pa1 = *(const float4*)(Ab + (size_t)(a_row0 + 64) * K + a_col);
    pb0 = *(const float4*)(Bb + (size_t)b_row0        * N + b_col);
    pb1 = *(const float4*)(Bb + (size_t)(b_row0 + 8)  * N + b_col);
    {
        uint4 u;
        u.x = f2tf32(pa0.x); u.y = f2tf32(pa0.y); u.z = f2tf32(pa0.z); u.w = f2tf32(pa0.w);
        *(uint4*)&As[0][a_row0 * AS_STR + a_col] = u;
        u.x = f2tf32(pa1.x); u.y = f2tf32(pa1.y); u.z = f2tf32(pa1.z); u.w = f2tf32(pa1.w);
        *(uint4*)&As[0][(a_row0 + 64) * AS_STR + a_col] = u;
        u.x = f2tf32(pb0.x); u.y = f2tf32(pb0.y); u.z = f2tf32(pb0.z); u.w = f2tf32(pb0.w);
        *(uint4*)&Bs[0][b_row0 * BS_STR + b_col] = u;
        u.x = f2tf32(pb1.x); u.y = f2tf32(pb1.y); u.z = f2tf32(pb1.z); u.w = f2tf32(pb1.w);
        *(uint4*)&Bs[0][(b_row0 + 8) * BS_STR + b_col] = u;
    }
    __syncthreads();

    for (int t = 0; t < ntiles; t++) {
        const int cur = t & 1, nxt = cur ^ 1;

        // prefetch next tile globals into regs (latency hidden by compute)
        if (t + 1 < ntiles) {
            const int k0 = (t + 1) * GBK;
            pa0 = *(const float4*)(Ab + (size_t)a_row0        * K + k0 + a_col);
            pa1 = *(const float4*)(Ab + (size_t)(a_row0 + 64) * K + k0 + a_col);
            pb0 = *(const float4*)(Bb + (size_t)(k0 + b_row0)     * N + b_col);
            pb1 = *(const float4*)(Bb + (size_t)(k0 + b_row0 + 8) * N + b_col);
        }

        // compute: 2 k-steps of 8
        #pragma unroll
        for (int ks = 0; ks < 2; ks++) {
            const int kb = ks * 8;
            unsigned a[4][4], b[4][2];
            #pragma unroll
            for (int i = 0; i < 4; i++) {
                const unsigned* ap = &As[cur][(wm + i * 16 + lr) * AS_STR + kb + lc];
                a[i][0] = ap[0];
                a[i][1] = ap[8 * AS_STR];
                a[i][2] = ap[4];
                a[i][3] = ap[8 * AS_STR + 4];
            }
            #pragma unroll
            for (int j = 0; j < 4; j++) {
                const unsigned* bp = &Bs[cur][(kb + lc) * BS_STR + wn + j * 8 + lr];
                b[j][0] = bp[0];
                b[j][1] = bp[4 * BS_STR];
            }
            #pragma unroll
            for (int i = 0; i < 4; i++)
                #pragma unroll
                for (int j = 0; j < 4; j++)
                    mma_tf32(acc[i][j], a[i], b[j]);
        }

        if (t + 1 < ntiles) {
            uint4 u;
            u.x = f2tf32(pa0.x); u.y = f2tf32(pa0.y); u.z = f2tf32(pa0.z); u.w = f2tf32(pa0.w);
            *(uint4*)&As[nxt][a_row0 * AS_STR + a_col] = u;
            u.x = f2tf32(pa1.x); u.y = f2tf32(pa1.y); u.z = f2tf32(pa1.z); u.w = f2tf32(pa1.w);
            *(uint4*)&As[nxt][(a_row0 + 64) * AS_STR + a_col] = u;
            u.x = f2tf32(pb0.x); u.y = f2tf32(pb0.y); u.z = f2tf32(pb0.z); u.w = f2tf32(pb0.w);
            *(uint4*)&Bs[nxt][b_row0 * BS_STR + b_col] = u;
            u.x = f2tf32(pb1.x); u.y = f2tf32(pb1.y); u.z = f2tf32(pb1.z); u.w = f2tf32(pb1.w);
            *(uint4*)&Bs[nxt][(b_row0 + 8) * BS_STR + b_col] = u;
            __syncthreads();
        }
    }

    // ---- epilogue: bias (+relu), float2 stores ----
    #pragma unroll
    for (int j = 0; j < 4; j++) {
        const int col = bx * GBN + wn + j * 8 + lc * 2;
        const float bv0 = bias[col], bv1 = bias[col + 1];
        #pragma unroll
        for (int i = 0; i < 4; i++) {
            const int row0 = by * GBM + wm + i * 16 + lr;
            float2 v0, v1;
            v0.x = acc[i][j][0] + bv0; v0.y = acc[i][j][1] + bv1;
            v1.x = acc[i][j][2] + bv0; v1.y = acc[i][j][3] + bv1;
            if (do_relu) {
                v0.x = fmaxf(v0.x, 0.f); v0.y = fmaxf(v0.y, 0.f);
                v1.x = fmaxf(v1.x, 0.f); v1.y = fmaxf(v1.y, 0.f);
            }
            *(float2*)(C + (size_t)row0 * N + col)       = v0;
            *(float2*)(C + (size_t)(row0 + 8) * N + col) = v1;
        }
    }
}

// ---------------- causal flash attention (fp32) ----------------
#define AT_BM 128
#define AT_BN 64

__global__ __launch_bounds__(128) void attention_kernel(
    const float* __restrict__ qkv, float* __restrict__ attn)
{
    __shared__ float Ks[AT_BN][DH];
    __shared__ float Vs[AT_BN][DH];

    const int bh = blockIdx.y;
    const int b  = bh >> 4;
    const int h  = bh & 15;
    const int q0 = blockIdx.x * AT_BM;
    const int tid = threadIdx.x;
    const int row = q0 + tid;

    const float* base = qkv + (size_t)b * LSEQ * (3 * DM);

    float q[DH];
    {
        const float* qp = base + (size_t)row * (3 * DM) + h * DH;
        #pragma unroll
        for (int d = 0; d < DH; d++) q[d] = qp[d] * 0.125f;
    }

    float o[DH];
    #pragma unroll
    for (int d = 0; d < DH; d++) o[d] = 0.f;
    float m = -INFINITY, lsum = 0.f;

    const int kmax = q0 + AT_BM;
    for (int j0 = 0; j0 < kmax; j0 += AT_BN) {
        __syncthreads();
        for (int i = tid; i < AT_BN * (DH / 4); i += AT_BM) {
            const int r = i >> 4, c4 = (i & 15) * 4;
            const float* kp = base + (size_t)(j0 + r) * (3 * DM) + DM + h * DH + c4;
            *(float4*)&Ks[r][c4] = *(const float4*)kp;
            *(float4*)&Vs[r][c4] = *(const float4*)(kp + DM);
        }
        __syncthreads();

        for (int jc = 0; jc < AT_BN; jc += 16) {
            if (j0 + jc > row) break;
            float s[16];
            #pragma unroll
            for (int jj = 0; jj < 16; jj++) {
                float a = 0.f;
                #pragma unroll
                for (int d4 = 0; d4 < DH / 4; d4++) {
                    float4 kv = *(float4*)&Ks[jc + jj][d4 * 4];
                    a += q[d4*4+0]*kv.x + q[d4*4+1]*kv.y + q[d4*4+2]*kv.z + q[d4*4+3]*kv.w;
                }
                s[jj] = (j0 + jc + jj <= row) ? a : -INFINITY;
            }
            float cmax = s[0];
            #pragma unroll
            for (int jj = 1; jj < 16; jj++) cmax = fmaxf(cmax, s[jj]);
            const float nm = fmaxf(m, cmax);
            const float scale = __expf(m - nm);
            m = nm;
            lsum *= scale;
            #pragma unroll
            for (int d = 0; d < DH; d++) o[d] *= scale;
            #pragma unroll
            for (int jj = 0; jj < 16; jj++) {
                const float p = __expf(s[jj] - nm);
                lsum += p;
                #pragma unroll
                for (int d4 = 0; d4 < DH / 4; d4++) {
                    float4 vv = *(float4*)&Vs[jc + jj][d4 * 4];
                    o[d4*4+0] += p * vv.x;
                    o[d4*4+1] += p * vv.y;
                    o[d4*4+2] += p * vv.z;
                    o[d4*4+3] += p * vv.w;
                }
            }
        }
    }

    const float inv = 1.f / lsum;
    float* op = attn + ((size_t)(b * LSEQ + row)) * DM + h * DH;
    #pragma unroll
    for (int d4 = 0; d4 < DH / 4; d4++) {
        float4 ov;
        ov.x = o[d4*4+0] * inv; ov.y = o[d4*4+1] * inv;
        ov.z = o[d4*4+2] * inv; ov.w = o[d4*4+3] * inv;
        *(float4*)(op + d4 * 4) = ov;
    }
}

// ---------------- fused residual + LayerNorm ----------------
__global__ __launch_bounds__(256) void ln_residual(
    const float* __restrict__ X, const float* __restrict__ Y,
    const float* __restrict__ gamma, const float* __restrict__ beta,
    float* __restrict__ out)
{
    __shared__ float sbuf[DM];
    __shared__ float red[8];

    const int row = blockIdx.x;
    const int tid = threadIdx.x;
    const int lane = tid & 31, warp = tid >> 5;
    const float* xr = X + (size_t)row * DM;
    const float* yr = Y + (size_t)row * DM;

    float lsum = 0.f;
    for (int i = tid; i < DM; i += 256) {
        const float v = xr[i] + yr[i];
        sbuf[i] = v;
        lsum += v;
    }
    #pragma unroll
    for (int off = 16; off > 0; off >>= 1) lsum += __shfl_down_sync(0xffffffffu, lsum, off);
    if (lane == 0) red[warp] = lsum;
    __syncthreads();
    float tot = 0.f;
    if (tid < 8) tot = red[tid];
    if (warp == 0) {
        #pragma unroll
        for (int off = 4; off > 0; off >>= 1) tot += __shfl_down_sync(0xffu, tot, off);
    }
    __shared__ float s_mean;
    if (tid == 0) s_mean = tot / (float)DM;
    __syncthreads();
    const float mean = s_mean;

    float lss = 0.f;
    for (int i = tid; i < DM; i += 256) {
        const float d = sbuf[i] - mean;
        lss += d * d;
    }
    #pragma unroll
    for (int off = 16; off > 0; off >>= 1) lss += __shfl_down_sync(0xffffffffu, lss, off);
    __syncthreads();
    if (lane == 0) red[warp] = lss;
    __syncthreads();
    float tot2 = 0.f;
    if (tid < 8) tot2 = red[tid];
    if (warp == 0) {
        #pragma unroll
        for (int off = 4; off > 0; off >>= 1) tot2 += __shfl_down_sync(0xffu, tot2, off);
    }
    __shared__ float s_inv;
    if (tid == 0) {
        const float var = tot2 / (float)(DM - 1);
        s_inv = 1.f / (sqrtf(var) + EPSV);
    }
    __syncthreads();
    const float inv = s_inv;

    float* orow = out + (size_t)row * DM;
    for (int i = tid; i < DM; i += 256)
        orow[i] = (sbuf[i] - mean) * inv * gamma[i] + beta[i];
}

// ---------------- launch ----------------
extern "C" void kernel_launch(void* const* d_in, const int* in_sizes, int n_in,
                              void* d_out, int out_size)
{
    const float* x    = (const float*)d_in[0];
    const float* Wqkv = (const float*)d_in[2];
    const float* bqkv = (const float*)d_in[3];
    const float* Wo   = (const float*)d_in[4];
    const float* bo   = (const float*)d_in[5];
    const float* W1   = (const float*)d_in[6];
    const float* b1   = (const float*)d_in[7];
    const float* W2   = (const float*)d_in[8];
    const float* b2   = (const float*)d_in[9];
    const float* ln1a = (const float*)d_in[10];
    const float* ln1b = (const float*)d_in[11];
    const float* ln2a = (const float*)d_in[12];
    const float* ln2b = (const float*)d_in[13];
    float* out = (float*)d_out;

    float *qkv, *attn, *proj, *x1, *hbuf, *mlp;
    cudaGetSymbolAddress((void**)&qkv,  g_qkv);
    cudaGetSymbolAddress((void**)&attn, g_attn);
    cudaGetSymbolAddress((void**)&proj, g_proj);
    cudaGetSymbolAddress((void**)&x1,   g_x1);
    cudaGetSymbolAddress((void**)&hbuf, g_h);
    cudaGetSymbolAddress((void**)&mlp,  g_mlp);

    // 1) QKV projection
    tgemm_bias<<<dim3(3 * DM / GBN, NT / GBM), 256>>>(x, Wqkv, bqkv, qkv, NT, 3 * DM, DM, 0);
    // 2) causal attention
    attention_kernel<<<dim3(LSEQ / AT_BM, 2 * NH), 128>>>(qkv, attn);
    // 3) output projection
    tgemm_bias<<<dim3(DM / GBN, NT / GBM), 256>>>(attn, Wo, bo, proj, NT, DM, DM, 0);
    // 4) LN1(x + attn_out)
    ln_residual<<<NT, 256>>>(x, proj, ln1a, ln1b, x1);
    // 5) FFN up + relu
    tgemm_bias<<<dim3(DF / GBN, NT / GBM), 256>>>(x1, W1, b1, hbuf, NT, DF, DM, 1);
    // 6) FFN down
    tgemm_bias<<<dim3(DM / GBN, NT / GBM), 256>>>(hbuf, W2, b2, mlp, NT, DM, DF, 0);
    // 7) LN2(x1 + mlp_out)
    ln_residual<<<NT, 256>>>(x1, mlp, ln2a, ln2b, out);
}

// round 3
// speedup vs baseline: 5.0131x; 2.7588x over previous
#include <cuda_runtime.h>
#include <cuda_fp16.h>
#include <math.h>

#define DM   1024
#define DF   4096
#define NT   4096
#define LSEQ 2048
#define NH   16
#define DH   64
#define EPSV 1e-6f

// ---------------- scratch ----------------
__device__ __half g_qkvh[NT * 3 * DM];   // qkv in half for attention
__device__ float  g_attn[NT * DM];
__device__ float  g_proj[NT * DM];
__device__ float  g_x1  [NT * DM];
__device__ __half g_h   [NT * DF];       // relu output in half (feeds W2)
__device__ float  g_mlp [NT * DM];

// ---------------- helpers ----------------
__device__ __forceinline__ unsigned sptr(const void* p) {
    return (unsigned)__cvta_generic_to_shared(p);
}
__device__ __forceinline__ void ldsm4(unsigned& r0, unsigned& r1, unsigned& r2, unsigned& r3, unsigned addr) {
    asm volatile("ldmatrix.sync.aligned.m8n8.x4.shared.b16 {%0,%1,%2,%3}, [%4];"
        : "=r"(r0), "=r"(r1), "=r"(r2), "=r"(r3) : "r"(addr));
}
__device__ __forceinline__ void ldsm4t(unsigned& r0, unsigned& r1, unsigned& r2, unsigned& r3, unsigned addr) {
    asm volatile("ldmatrix.sync.aligned.m8n8.x4.trans.shared.b16 {%0,%1,%2,%3}, [%4];"
        : "=r"(r0), "=r"(r1), "=r"(r2), "=r"(r3) : "r"(addr));
}
__device__ __forceinline__ void mma_f16(float c[4], const unsigned a[4], const unsigned b0, const unsigned b1) {
    asm volatile(
        "mma.sync.aligned.m16n8k16.row.col.f32.f16.f16.f32 "
        "{%0,%1,%2,%3}, {%4,%5,%6,%7}, {%8,%9}, {%0,%1,%2,%3};"
        : "+f"(c[0]), "+f"(c[1]), "+f"(c[2]), "+f"(c[3])
        : "r"(a[0]), "r"(a[1]), "r"(a[2]), "r"(a[3]), "r"(b0), "r"(b1));
}
__device__ __forceinline__ unsigned pack2(float x, float y) {
    __half2 h = __floats2half2_rn(x, y);
    return *(unsigned*)&h;
}

// ================= fp16 tensor-core GEMM =================
// C[M,N] = A[M,K] @ B[K,N] + bias (fp32 in, fp32 accumulate)
// BM=BN=128, BK=16; 256 thr, 8 warps 2x4; warp tile 64x32.
#define GBM 128
#define GBN 128
#define GBK 16
#define AS_STR 24    // half stride
#define BS_STR 136   // half stride

template<bool RELU, bool HOUT>
__global__ __launch_bounds__(256) void hgemm_bias(
    const float* __restrict__ A, const float* __restrict__ B,
    const float* __restrict__ bias, void* __restrict__ Cv,
    int M, int N, int K)
{
    __shared__ __half As[2][GBM * AS_STR];
    __shared__ __half Bs[2][GBK * BS_STR];

    const int tid = threadIdx.x;
    const int bx = blockIdx.x, by = blockIdx.y;
    const int lane = tid & 31, warp = tid >> 5;
    const int wm = (warp >> 2) * 64;
    const int wn = (warp & 3) * 32;
    const int lr = lane >> 2, lc = lane & 3;

    // staging: A 128x16 (8 halves/thread), B 16x128 (8 halves/thread)
    const int a_row = tid >> 1,  a_col = (tid & 1) * 8;
    const int b_row = tid >> 4,  b_col = (tid & 15) * 8;

    const float* Ab = A + (size_t)(by * GBM) * K;
    const float* Bb = B + bx * GBN;

    float acc[4][4][4];
    #pragma unroll
    for (int i = 0; i < 4; i++)
        #pragma unroll
        for (int j = 0; j < 4; j++)
            #pragma unroll
            for (int r = 0; r < 4; r++) acc[i][j][r] = 0.f;

    const int ntiles = K / GBK;
    float4 pa0, pa1, pb0, pb1;

    // load tile 0
    pa0 = *(const float4*)(Ab + (size_t)a_row * K + a_col);
    pa1 = *(const float4*)(Ab + (size_t)a_row * K + a_col + 4);
    pb0 = *(const float4*)(Bb + (size_t)b_row * N + b_col);
    pb1 = *(const float4*)(Bb + (size_t)b_row * N + b_col + 4);
    {
        uint4 ua = make_uint4(pack2(pa0.x,pa0.y), pack2(pa0.z,pa0.w), pack2(pa1.x,pa1.y), pack2(pa1.z,pa1.w));
        *(uint4*)&As[0][a_row * AS_STR + a_col] = ua;
        uint4 ub = make_uint4(pack2(pb0.x,pb0.y), pack2(pb0.z,pb0.w), pack2(pb1.x,pb1.y), pack2(pb1.z,pb1.w));
        *(uint4*)&Bs[0][b_row * BS_STR + b_col] = ub;
    }
    __syncthreads();

    for (int t = 0; t < ntiles; t++) {
        const int cur = t & 1, nxt = cur ^ 1;

        if (t + 1 < ntiles) {
            const int k0 = (t + 1) * GBK;
            pa0 = *(const float4*)(Ab + (size_t)a_row * K + k0 + a_col);
            pa1 = *(const float4*)(Ab + (size_t)a_row * K + k0 + a_col + 4);
            pb0 = *(const float4*)(Bb + (size_t)(k0 + b_row) * N + b_col);
            pb1 = *(const float4*)(Bb + (size_t)(k0 + b_row) * N + b_col + 4);
        }

        // fragments
        unsigned a[4][4], b[2][4];
        #pragma unroll
        for (int i = 0; i < 4; i++)
            ldsm4(a[i][0], a[i][1], a[i][2], a[i][3],
                  sptr(&As[cur][(wm + i * 16 + (lane & 15)) * AS_STR + (lane >> 4) * 8]));
        #pragma unroll
        for (int j2 = 0; j2 < 2; j2++)
            ldsm4t(b[j2][0], b[j2][1], b[j2][2], b[j2][3],
                   sptr(&Bs[cur][(lane & 15) * BS_STR + wn + j2 * 16 + (lane >> 4) * 8]));

        #pragma unroll
        for (int i = 0; i < 4; i++)
            #pragma unroll
            for (int j2 = 0; j2 < 2; j2++) {
                mma_f16(acc[i][2*j2],   a[i], b[j2][0], b[j2][1]);
                mma_f16(acc[i][2*j2+1], a[i], b[j2][2], b[j2][3]);
            }

        if (t + 1 < ntiles) {
            uint4 ua = make_uint4(pack2(pa0.x,pa0.y), pack2(pa0.z,pa0.w), pack2(pa1.x,pa1.y), pack2(pa1.z,pa1.w));
            *(uint4*)&As[nxt][a_row * AS_STR + a_col] = ua;
            uint4 ub = make_uint4(pack2(pb0.x,pb0.y), pack2(pb0.z,pb0.w), pack2(pb1.x,pb1.y), pack2(pb1.z,pb1.w));
            *(uint4*)&Bs[nxt][b_row * BS_STR + b_col] = ub;
            __syncthreads();
        }
    }

    // epilogue
    #pragma unroll
    for (int j = 0; j < 4; j++) {
        const int col = bx * GBN + wn + j * 8 + lc * 2;
        const float bv0 = bias[col], bv1 = bias[col + 1];
        #pragma unroll
        for (int i = 0; i < 4; i++) {
            const int row0 = by * GBM + wm + i * 16 + lr;
            float v0 = acc[i][j][0] + bv0, v1 = acc[i][j][1] + bv1;
            float v2 = acc[i][j][2] + bv0, v3 = acc[i][j][3] + bv1;
            if (RELU) {
                v0 = fmaxf(v0, 0.f); v1 = fmaxf(v1, 0.f);
                v2 = fmaxf(v2, 0.f); v3 = fmaxf(v3, 0.f);
            }
            if (HOUT) {
                __half* C = (__half*)Cv;
                *(__half2*)(C + (size_t)row0 * N + col)       = __floats2half2_rn(v0, v1);
                *(__half2*)(C + (size_t)(row0 + 8) * N + col) = __floats2half2_rn(v2, v3);
            } else {
                float* C = (float*)Cv;
                *(float2*)(C + (size_t)row0 * N + col)       = make_float2(v0, v1);
                *(float2*)(C + (size_t)(row0 + 8) * N + col) = make_float2(v2, v3);
            }
        }
    }
}

// ================= fp16 tensor-core causal flash attention =================
// qkvh: [NT][3*DM] half, per-token layout [3][H][DH]
// 64 q-rows/block, 4 warps x m16; 64-key tiles.
#define QS_STR 72

__global__ __launch_bounds__(128) void attention_mma(
    const __half* __restrict__ qkvh, float* __restrict__ attn)
{
    __shared__ __half Qs[64 * QS_STR];
    __shared__ __half Ks[64 * QS_STR];
    __shared__ __half Vs[64 * QS_STR];

    const int tid = threadIdx.x;
    const int lane = tid & 31, warp = tid >> 5;
    const int bh = blockIdx.y;
    const int b = bh >> 4, h = bh & 15;
    const int q0 = blockIdx.x * 64;
    const int lr = lane >> 2, lc = lane & 3;

    const __half* base = qkvh + (size_t)b * LSEQ * (3 * DM);

    // load Q tile (64 rows x 64 halves)
    for (int i = tid; i < 64 * 8; i += 128) {
        const int r = i >> 3, c8 = (i & 7) * 8;
        *(uint4*)&Qs[r * QS_STR + c8] =
            *(const uint4*)(base + (size_t)(q0 + r) * (3 * DM) + h * DH + c8);
    }
    __syncthreads();

    // Q fragments: 4 k-steps of 16
    unsigned qf[4][4];
    #pragma unroll
    for (int ks = 0; ks < 4; ks++)
        ldsm4(qf[ks][0], qf[ks][1], qf[ks][2], qf[ks][3],
              sptr(&Qs[(warp * 16 + (lane & 15)) * QS_STR + ks * 16 + (lane >> 4) * 8]));

    float o[8][4];
    #pragma unroll
    for (int d = 0; d < 8; d++)
        #pragma unroll
        for (int r = 0; r < 4; r++) o[d][r] = 0.f;
    float mrow[2] = {-INFINITY, -INFINITY};
    float lrow[2] = {0.f, 0.f};

    const int row0 = q0 + warp * 16 + lr;
    const int row1 = row0 + 8;
    const int ntile = blockIdx.x + 1;

    for (int t = 0; t < ntile; t++) {
        const int j0 = t * 64;
        __syncthreads();
        for (int i = tid; i < 64 * 8; i += 128) {
            const int r = i >> 3, c8 = (i & 7) * 8;
            const __half* kp = base + (size_t)(j0 + r) * (3 * DM) + DM + h * DH + c8;
            *(uint4*)&Ks[r * QS_STR + c8] = *(const uint4*)kp;
            *(uint4*)&Vs[r * QS_STR + c8] = *(const uint4*)(kp + DM);
        }
        __syncthreads();

        // ---- S = Q @ K^T ----
        float s[8][4];
        #pragma unroll
        for (int jt2 = 0; jt2 < 4; jt2++) {
            #pragma unroll
            for (int r = 0; r < 4; r++) { s[2*jt2][r] = 0.f; s[2*jt2+1][r] = 0.f; }
            #pragma unroll
            for (int ks = 0; ks < 4; ks++) {
                unsigned k0r, k1r, k2r, k3r;
                ldsm4(k0r, k1r, k2r, k3r,
                      sptr(&Ks[(jt2 * 16 + (lane & 15)) * QS_STR + ks * 16 + (lane >> 4) * 8]));
                mma_f16(s[2*jt2],   qf[ks], k0r, k2r);
                mma_f16(s[2*jt2+1], qf[ks], k1r, k3r);
            }
        }

        // scale + causal mask (only diagonal tile)
        const bool diag = (t == ntile - 1);
        #pragma unroll
        for (int jn = 0; jn < 8; jn++) {
            const int col = j0 + jn * 8 + lc * 2;
            s[jn][0] *= 0.125f; s[jn][1] *= 0.125f;
            s[jn][2] *= 0.125f; s[jn][3] *= 0.125f;
            if (diag) {
                if (col     > row0) s[jn][0] = -INFINITY;
                if (col + 1 > row0) s[jn][1] = -INFINITY;
                if (col     > row1) s[jn][2] = -INFINITY;
                if (col + 1 > row1) s[jn][3] = -INFINITY;
            }
        }

        // row max
        float t0 = s[0][0], t1 = s[0][2];
        #pragma unroll
        for (int jn = 0; jn < 8; jn++) {
            t0 = fmaxf(t0, fmaxf(s[jn][0], s[jn][1]));
            t1 = fmaxf(t1, fmaxf(s[jn][2], s[jn][3]));
        }
        t0 = fmaxf(t0, __shfl_xor_sync(0xffffffffu, t0, 1));
        t0 = fmaxf(t0, __shfl_xor_sync(0xffffffffu, t0, 2));
        t1 = fmaxf(t1, __shfl_xor_sync(0xffffffffu, t1, 1));
        t1 = fmaxf(t1, __shfl_xor_sync(0xffffffffu, t1, 2));

        const float mn0 = fmaxf(mrow[0], t0), mn1 = fmaxf(mrow[1], t1);
        const float sc0 = __expf(mrow[0] - mn0), sc1 = __expf(mrow[1] - mn1);
        mrow[0] = mn0; mrow[1] = mn1;
        lrow[0] *= sc0; lrow[1] *= sc1;
        #pragma unroll
        for (int d = 0; d < 8; d++) {
            o[d][0] *= sc0; o[d][1] *= sc0;
            o[d][2] *= sc1; o[d][3] *= sc1;
        }

        // p = exp(s - m)
        #pragma unroll
        for (int jn = 0; jn < 8; jn++) {
            s[jn][0] = __expf(s[jn][0] - mn0);
            s[jn][1] = __expf(s[jn][1] - mn0);
            s[jn][2] = __expf(s[jn][2] - mn1);
            s[jn][3] = __expf(s[jn][3] - mn1);
            lrow[0] += s[jn][0] + s[jn][1];
            lrow[1] += s[jn][2] + s[jn][3];
        }

        // ---- O += P @ V ----
        #pragma unroll
        for (int jt2 = 0; jt2 < 4; jt2++) {
            unsigned a[4];
            a[0] = pack2(s[2*jt2][0],   s[2*jt2][1]);
            a[1] = pack2(s[2*jt2][2],   s[2*jt2][3]);
            a[2] = pack2(s[2*jt2+1][0], s[2*jt2+1][1]);
            a[3] = pack2(s[2*jt2+1][2], s[2*jt2+1][3]);
            #pragma unroll
            for (int d2 = 0; d2 < 4; d2++) {
                unsigned v0, v1, v2, v3;
                ldsm4t(v0, v1, v2, v3,
                       sptr(&Vs[(jt2 * 16 + (lane & 15)) * QS_STR + d2 * 16 + (lane >> 4) * 8]));
                mma_f16(o[2*d2],   a, v0, v1);
                mma_f16(o[2*d2+1], a, v2, v3);
            }
        }
    }

    // normalize + write
    lrow[0] += __shfl_xor_sync(0xffffffffu, lrow[0], 1);
    lrow[0] += __shfl_xor_sync(0xffffffffu, lrow[0], 2);
    lrow[1] += __shfl_xor_sync(0xffffffffu, lrow[1], 1);
    lrow[1] += __shfl_xor_sync(0xffffffffu, lrow[1], 2);
    const float inv0 = 1.f / lrow[0], inv1 = 1.f / lrow[1];

    float* op0 = attn + ((size_t)(b * LSEQ + row0)) * DM + h * DH;
    float* op1 = attn + ((size_t)(b * LSEQ + row1)) * DM + h * DH;
    #pragma unroll
    for (int d = 0; d < 8; d++) {
        const int col = d * 8 + lc * 2;
        *(float2*)(op0 + col) = make_float2(o[d][0] * inv0, o[d][1] * inv0);
        *(float2*)(op1 + col) = make_float2(o[d][2] * inv1, o[d][3] * inv1);
    }
}

// ---------------- fused residual + LayerNorm ----------------
__global__ __launch_bounds__(256) void ln_residual(
    const float* __restrict__ X, const float* __restrict__ Y,
    const float* __restrict__ gamma, const float* __restrict__ beta,
    float* __restrict__ out)
{
    __shared__ float sbuf[DM];
    __shared__ float red[8];

    const int row = blockIdx.x;
    const int tid = threadIdx.x;
    const int lane = tid & 31, warp = tid >> 5;
    const float* xr = X + (size_t)row * DM;
    const float* yr = Y + (size_t)row * DM;

    float lsum = 0.f;
    for (int i = tid; i < DM; i += 256) {
        const float v = xr[i] + yr[i];
        sbuf[i] = v;
        lsum += v;
    }
    #pragma unroll
    for (int off = 16; off > 0; off >>= 1) lsum += __shfl_down_sync(0xffffffffu, lsum, off);
    if (lane == 0) red[warp] = lsum;
    __syncthreads();
    float tot = 0.f;
    if (tid < 8) tot = red[tid];
    if (warp == 0) {
        #pragma unroll
        for (int off = 4; off > 0; off >>= 1) tot += __shfl_down_sync(0xffu, tot, off);
    }
    __shared__ float s_mean;
    if (tid == 0) s_mean = tot / (float)DM;
    __syncthreads();
    const float mean = s_mean;

    float lss = 0.f;
    for (int i = tid; i < DM; i += 256) {
        const float d = sbuf[i] - mean;
        lss += d * d;
    }
    #pragma unroll
    for (int off = 16; off > 0; off >>= 1) lss += __shfl_down_sync(0xffffffffu, lss, off);
    __syncthreads();
    if (lane == 0) red[warp] = lss;
    __syncthreads();
    float tot2 = 0.f;
    if (tid < 8) tot2 = red[tid];
    if (warp == 0) {
        #pragma unroll
        for (int off = 4; off > 0; off >>= 1) tot2 += __shfl_down_sync(0xffu, tot2, off);
    }
    __shared__ float s_inv;
    if (tid == 0) {
        const float var = tot2 / (float)(DM - 1);
        s_inv = 1.f / (sqrtf(var) + EPSV);
    }
    __syncthreads();
    const float inv = s_inv;

    float* orow = out + (size_t)row * DM;
    for (int i = tid; i < DM; i += 256)
        orow[i] = (sbuf[i] - mean) * inv * gamma[i] + beta[i];
}

// ---------------- launch ----------------
extern "C" void kernel_launch(void* const* d_in, const int* in_sizes, int n_in,
                              void* d_out, int out_size)
{
    const float* x    = (const float*)d_in[0];
    const float* Wqkv = (const float*)d_in[2];
    const float* bqkv = (const float*)d_in[3];
    const float* Wo   = (const float*)d_in[4];
    const float* bo   = (const float*)d_in[5];
    const float* W1   = (const float*)d_in[6];
    const float* b1   = (const float*)d_in[7];
    const float* W2   = (const float*)d_in[8];
    const float* b2   = (const float*)d_in[9];
    const float* ln1a = (const float*)d_in[10];
    const float* ln1b = (const float*)d_in[11];
    const float* ln2a = (const float*)d_in[12];
    const float* ln2b = (const float*)d_in[13];
    float* out = (float*)d_out;

    __half *qkvh, *hbuf;
    float *attn, *proj, *x1, *mlp;
    cudaGetSymbolAddress((void**)&qkvh, g_qkvh);
    cudaGetSymbolAddress((void**)&attn, g_attn);
    cudaGetSymbolAddress((void**)&proj, g_proj);
    cudaGetSymbolAddress((void**)&x1,   g_x1);
    cudaGetSymbolAddress((void**)&hbuf, g_h);
    cudaGetSymbolAddress((void**)&mlp,  g_mlp);

    // 1) QKV projection -> half
    hgemm_bias<false, true><<<dim3(3 * DM / GBN, NT / GBM), 256>>>(x, Wqkv, bqkv, qkvh, NT, 3 * DM, DM);
    // 2) causal attention (tensor core)
    attention_mma<<<dim3(LSEQ / 64, 2 * NH), 128>>>(qkvh, attn);
    // 3) output projection
    hgemm_bias<false, false><<<dim3(DM / GBN, NT / GBM), 256>>>(attn, Wo, bo, proj, NT, DM, DM);
    // 4) LN1
    ln_residual<<<NT, 256>>>(x, proj, ln1a, ln1b, x1);
    // 5) FFN up + relu -> half
    hgemm_bias<true, true><<<dim3(DF / GBN, NT / GBM), 256>>>(x1, W1, b1, hbuf, NT, DF, DM);
    // 6) FFN down (A is half -> need float A; W2 GEMM reads half A)
    // NOTE: hgemm reads float A; so convert path: use dedicated GEMM below.
    // We instead keep h in half only for storage; W2 GEMM must read half A.
    // Handled by hgemm_a16 below.
    {
        extern __global__ void hgemm_a16(const __half*, const float*, const float*, float*, int, int, int);
        hgemm_a16<<<dim3(DM / GBN, NT / GBM), 256>>>(hbuf, W2, b2, mlp, NT, DM, DF);
    }
    // 7) LN2 -> output
    ln_residual<<<NT, 256>>>(x1, mlp, ln2a, ln2b, out);
}

// ================= GEMM with half A operand (for W2) =================
__global__ __launch_bounds__(256) void hgemm_a16(
    const __half* __restrict__ A, const float* __restrict__ B,
    const float* __restrict__ bias, float* __restrict__ C,
    int M, int N, int K)
{
    __shared__ __half As[2][GBM * AS_STR];
    __shared__ __half Bs[2][GBK * BS_STR];

    const int tid = threadIdx.x;
    const int bx = blockIdx.x, by = blockIdx.y;
    const int lane = tid & 31, warp = tid >> 5;
    const int wm = (warp >> 2) * 64;
    const int wn = (warp & 3) * 32;
    const int lr = lane >> 2, lc = lane & 3;

    const int a_row = tid >> 1,  a_col = (tid & 1) * 8;
    const int b_row = tid >> 4,  b_col = (tid & 15) * 8;

    const __half* Ab = A + (size_t)(by * GBM) * K;
    const float*  Bb = B + bx * GBN;

    float acc[4][4][4];
    #pragma unroll
    for (int i = 0; i < 4; i++)
        #pragma unroll
        for (int j = 0; j < 4; j++)
            #pragma unroll
            for (int r = 0; r < 4; r++) acc[i][j][r] = 0.f;

    const int ntiles = K / GBK;
    uint4 pa; float4 pb0, pb1;

    pa  = *(const uint4*)(Ab + (size_t)a_row * K + a_col);
    pb0 = *(const float4*)(Bb + (size_t)b_row * N + b_col);
    pb1 = *(const float4*)(Bb + (size_t)b_row * N + b_col + 4);
    {
        *(uint4*)&As[0][a_row * AS_STR + a_col] = pa;
        uint4 ub = make_uint4(pack2(pb0.x,pb0.y), pack2(pb0.z,pb0.w), pack2(pb1.x,pb1.y), pack2(pb1.z,pb1.w));
        *(uint4*)&Bs[0][b_row * BS_STR + b_col] = ub;
    }
    __syncthreads();

    for (int t = 0; t < ntiles; t++) {
        const int cur = t & 1, nxt = cur ^ 1;

        if (t + 1 < ntiles) {
            const int k0 = (t + 1) * GBK;
            pa  = *(const uint4*)(Ab + (size_t)a_row * K + k0 + a_col);
            pb0 = *(const float4*)(Bb + (size_t)(k0 + b_row) * N + b_col);
            pb1 = *(const float4*)(Bb + (size_t)(k0 + b_row) * N + b_col + 4);
        }

        unsigned a[4][4], b[2][4];
        #pragma unroll
        for (int i = 0; i < 4; i++)
            ldsm4(a[i][0], a[i][1], a[i][2], a[i][3],
                  sptr(&As[cur][(wm + i * 16 + (lane & 15)) * AS_STR + (lane >> 4) * 8]));
        #pragma unroll
        for (int j2 = 0; j2 < 2; j2++)
            ldsm4t(b[j2][0], b[j2][1], b[j2][2], b[j2][3],
                   sptr(&Bs[cur][(lane & 15) * BS_STR + wn + j2 * 16 + (lane >> 4) * 8]));

        #pragma unroll
        for (int i = 0; i < 4; i++)
            #pragma unroll
            for (int j2 = 0; j2 < 2; j2++) {
                mma_f16(acc[i][2*j2],   a[i], b[j2][0], b[j2][1]);
                mma_f16(acc[i][2*j2+1], a[i], b[j2][2], b[j2][3]);
            }

        if (t + 1 < ntiles) {
            *(uint4*)&As[nxt][a_row * AS_STR + a_col] = pa;
            uint4 ub = make_uint4(pack2(pb0.x,pb0.y), pack2(pb0.z,pb0.w), pack2(pb1.x,pb1.y), pack2(pb1.z,pb1.w));
            *(uint4*)&Bs[nxt][b_row * BS_STR + b_col] = ub;
            __syncthreads();
        }
    }

    #pragma unroll
    for (int j = 0; j < 4; j++) {
        const int col = bx * GBN + wn + j * 8 + lc * 2;
        const float bv0 = bias[col], bv1 = bias[col + 1];
        #pragma unroll
        for (int i = 0; i < 4; i++) {
            const int row0 = by * GBM + wm + i * 16 + lr;
            *(float2*)(C + (size_t)row0 * N + col) =
                make_float2(acc[i][j][0] + bv0, acc[i][j][1] + bv1);
            *(float2*)(C + (size_t)(row0 + 8) * N + col) =
                make_float2(acc[i][j][2] + bv0, acc[i][j][3] + bv1);
        }
    }
}